// round 4
// baseline (speedup 1.0000x reference)
#include <cuda_runtime.h>
#include <cuda_bf16.h>
#include <cstdint>
#include <cstddef>

#define DEV_INLINE __device__ __forceinline__

// ---------------- problem constants (fixed shapes) ----------------
constexpr int N_ROWS = 4096;
constexpr int DIM    = 512;
constexpr int NCLS   = 50000;
constexpr float S_SCALE    = 30.0f;
constexpr float MARGIN_COS = 0.9210609940028851f;  // cos(0.4)
constexpr float MARGIN_SIN = 0.3894183423086505f;  // sin(0.4)

// ---------------- GEMM tiling ----------------
constexpr int BM = 128;
constexpr int BN = 256;
constexpr int BK = 64;                 // 64 bf16 = 128B rows (SW128 atom)
constexpr int NKI = DIM / BK;          // 8 k-iterations
constexpr int NSTAGE = 3;
constexpr int MTILES = N_ROWS / BM;                  // 32
constexpr int NTILES = (NCLS + BN - 1) / BN;         // 196 (last masked)

constexpr uint32_t A_STAGE = BM * 128;               // 16384
constexpr uint32_t B_STAGE = BN * 128;               // 32768
constexpr uint32_t SMEM_B0   = NSTAGE * A_STAGE;     // 49152
constexpr uint32_t SMEM_EXCL = SMEM_B0 + NSTAGE * B_STAGE;   // 147456
constexpr uint32_t SMEM_TG   = SMEM_EXCL + BM * 4;           // 147968
constexpr uint32_t SMEM_TOTAL = SMEM_TG + BM * 4;            // 148480

// ---------------- device scratch (allocation-free rule) ----------------
__device__ __nv_bfloat16 g_xbf[(size_t)N_ROWS * DIM];   // normalized x, bf16
__device__ __nv_bfloat16 g_wbf[(size_t)NCLS * DIM];     // W, bf16 (51MB, mostly L2)
__device__ float g_excl[N_ROWS];
__device__ float g_tgt[N_ROWS];
__device__ float g_sum;

// ---------------- helpers ----------------
DEV_INLINE uint32_t smem_u32(const void* p) { return (uint32_t)__cvta_generic_to_shared(p); }
DEV_INLINE uint32_t swz(uint32_t o) { return o ^ ((o >> 3) & 0x70); }

DEV_INLINE void cp16(uint32_t dst, const void* src) {
    asm volatile("cp.async.cg.shared.global [%0], [%1], 16;" :: "r"(dst), "l"(src));
}

DEV_INLINE void ldm_x4(uint32_t& r0, uint32_t& r1, uint32_t& r2, uint32_t& r3,
                       uint32_t addr) {
    asm volatile("ldmatrix.sync.aligned.m8n8.x4.shared.b16 {%0,%1,%2,%3}, [%4];"
                 : "=r"(r0), "=r"(r1), "=r"(r2), "=r"(r3) : "r"(addr));
}

DEV_INLINE void mma_bf16(float* d, const uint32_t* a, uint32_t b0, uint32_t b1) {
    asm volatile(
        "mma.sync.aligned.m16n8k16.row.col.f32.bf16.bf16.f32 "
        "{%0,%1,%2,%3}, {%4,%5,%6,%7}, {%8,%9}, {%0,%1,%2,%3};"
        : "+f"(d[0]), "+f"(d[1]), "+f"(d[2]), "+f"(d[3])
        : "r"(a[0]), "r"(a[1]), "r"(a[2]), "r"(a[3]), "r"(b0), "r"(b1));
}

// ---------------- kernel 0: zero the loss accumulator ----------------
__global__ void zero_sum_kernel() { g_sum = 0.0f; }

// ---------------- kernel 1: W fp32 -> bf16 ----------------
__global__ void conv_w_kernel(const float* __restrict__ W) {
    size_t i = ((size_t)blockIdx.x * blockDim.x + threadIdx.x) * 4;
    float4 v = *reinterpret_cast<const float4*>(W + i);
    *reinterpret_cast<__nv_bfloat162*>(g_wbf + i)     = __floats2bfloat162_rn(v.x, v.y);
    *reinterpret_cast<__nv_bfloat162*>(g_wbf + i + 2) = __floats2bfloat162_rn(v.z, v.w);
}

// ---------------- kernel 2: normalize x rows -> bf16 (+ zero excl) ----------------
__global__ void prep_x_kernel(const float* __restrict__ x) {
    int row = blockIdx.x * 8 + (threadIdx.x >> 5);
    int lid = threadIdx.x & 31;
    const float* xr = x + (size_t)row * DIM;
    float s = 0.0f;
#pragma unroll
    for (int j = 0; j < 16; j++) { float v = xr[lid + j * 32]; s += v * v; }
#pragma unroll
    for (int o = 16; o; o >>= 1) s += __shfl_xor_sync(0xFFFFFFFFu, s, o);
    float rn = rsqrtf(s);
    __nv_bfloat16* outr = g_xbf + (size_t)row * DIM;
#pragma unroll
    for (int j = 0; j < 16; j++) {
        int d = lid + j * 32;
        outr[d] = __float2bfloat16(xr[d] * rn);
    }
    if (lid == 0) g_excl[row] = 0.0f;   // re-zero on every graph replay
}

// ---------------- kernel 3: HMMA GEMM + fused arcface epilogue ----------------
// BM=128 x BN=256, 8 warps in 2x4 grid, 64x64 warp tiles, 3-stage cp.async.
__global__ void __launch_bounds__(256, 1)
arc_gemm_kernel(const int* __restrict__ target) {
    extern __shared__ char smem[];
    const uint32_t sb = smem_u32(smem);
    const uint32_t sA = sb;
    const uint32_t sB = sb + SMEM_B0;
    float* s_excl = reinterpret_cast<float*>(smem + SMEM_EXCL);
    int*   s_tg   = reinterpret_cast<int*>(smem + SMEM_TG);

    const int tid = threadIdx.x;
    const int lid = tid & 31;
    const int wid = tid >> 5;
    const int wm  = wid & 1;          // 0..1  (m, 64 rows each)
    const int wn  = wid >> 1;         // 0..3  (n, 64 cols each)
    const int rbase = blockIdx.x * BM;
    const int cbase = blockIdx.y * BN;

    if (tid < BM) {
        s_excl[tid] = 0.0f;
        s_tg[tid]   = target[rbase + tid];
    }

    // cp.async chunking: 16B chunks; chunk = tid + i*256; row = chunk>>3, kb = chunk&7
    const int c_row = tid >> 3;
    const int c_kb  = tid & 7;

    // ldmatrix address components (within-stage byte offsets; swizzled at use)
    const uint32_t a_row  = wm * 64 + (lid & 15);
    const uint32_t a_koff = (lid >> 4) * 16;
    const uint32_t b_row  = wn * 64 + (lid & 7) + ((lid >> 4) & 1) * 8;
    const uint32_t b_koff = ((lid >> 3) & 1) * 16;

    float acc[4][8][4];
#pragma unroll
    for (int mt = 0; mt < 4; mt++)
#pragma unroll
        for (int nt = 0; nt < 8; nt++)
#pragma unroll
            for (int j = 0; j < 4; j++) acc[mt][nt][j] = 0.0f;

    // ---- prefetch stages 0 and 1 ----
#pragma unroll
    for (int pk = 0; pk < 2; pk++) {
        const int k0 = pk * BK;
        const uint32_t sa = sA + pk * A_STAGE;
        const uint32_t sbb = sB + pk * B_STAGE;
        const __nv_bfloat16* xs = g_xbf + (size_t)rbase * DIM + k0;
#pragma unroll
        for (int i = 0; i < 4; i++) {
            int row = c_row + i * 32;
            cp16(sa + swz(row * 128 + c_kb * 16), xs + (size_t)row * DIM + c_kb * 8);
        }
        const __nv_bfloat16* ws = g_wbf + k0;
#pragma unroll
        for (int i = 0; i < 8; i++) {
            int row = c_row + i * 32;
            int c = cbase + row; c = (c < NCLS) ? c : (NCLS - 1);
            cp16(sbb + swz(row * 128 + c_kb * 16), ws + (size_t)c * DIM + c_kb * 8);
        }
        asm volatile("cp.async.commit_group;" ::: "memory");
    }

    int stage = 0;
    for (int k = 0; k < NKI; k++) {
        if (k == NKI - 1)
            asm volatile("cp.async.wait_group 0;" ::: "memory");
        else
            asm volatile("cp.async.wait_group 1;" ::: "memory");
        __syncthreads();

        if (k + 2 < NKI) {
            const int ps = (stage + 2 >= NSTAGE) ? stage + 2 - NSTAGE : stage + 2;
            const int k0 = (k + 2) * BK;
            const uint32_t sa = sA + ps * A_STAGE;
            const uint32_t sbb = sB + ps * B_STAGE;
            const __nv_bfloat16* xs = g_xbf + (size_t)rbase * DIM + k0;
#pragma unroll
            for (int i = 0; i < 4; i++) {
                int row = c_row + i * 32;
                cp16(sa + swz(row * 128 + c_kb * 16), xs + (size_t)row * DIM + c_kb * 8);
            }
            const __nv_bfloat16* ws = g_wbf + k0;
#pragma unroll
            for (int i = 0; i < 8; i++) {
                int row = c_row + i * 32;
                int c = cbase + row; c = (c < NCLS) ? c : (NCLS - 1);
                cp16(sbb + swz(row * 128 + c_kb * 16), ws + (size_t)c * DIM + c_kb * 8);
            }
            asm volatile("cp.async.commit_group;" ::: "memory");
        }

        const uint32_t abase = sA + stage * A_STAGE;
        const uint32_t bbase = sB + stage * B_STAGE;
        // ---- compute BK=64 as 4 k-steps of 16 ----
#pragma unroll
        for (int kk = 0; kk < 4; kk++) {
            uint32_t a[4][4];
#pragma unroll
            for (int mt = 0; mt < 4; mt++) {
                uint32_t addr = abase + swz((a_row + mt * 16) * 128 + kk * 32 + a_koff);
                ldm_x4(a[mt][0], a[mt][1], a[mt][2], a[mt][3], addr);
            }
            uint32_t b[8][2];
#pragma unroll
            for (int np = 0; np < 4; np++) {
                uint32_t r0, r1, r2, r3;
                uint32_t addr = bbase + swz((b_row + np * 16) * 128 + kk * 32 + b_koff);
                ldm_x4(r0, r1, r2, r3, addr);
                b[np * 2][0] = r0;     b[np * 2][1] = r1;
                b[np * 2 + 1][0] = r2; b[np * 2 + 1][1] = r3;
            }
#pragma unroll
            for (int mt = 0; mt < 4; mt++)
#pragma unroll
                for (int nt = 0; nt < 8; nt++)
                    mma_bf16(acc[mt][nt], a[mt], b[nt][0], b[nt][1]);
        }
        stage = (stage + 1 >= NSTAGE) ? 0 : stage + 1;
    }
    __syncthreads();

    // ---- fused epilogue from accumulator registers ----
    // c-frag: d0=(r,c0) d1=(r,c0+1) d2=(r+8,c0) d3=(r+8,c0+1); r=lid>>2, c0=2*(lid&3)
#pragma unroll
    for (int mt = 0; mt < 4; mt++) {
#pragma unroll
        for (int h = 0; h < 2; h++) {
            int rloc = wm * 64 + mt * 16 + (lid >> 2) + h * 8;
            int tg = s_tg[rloc];
            float s = 0.0f;
#pragma unroll
            for (int nt = 0; nt < 8; nt++) {
#pragma unroll
                for (int j = 0; j < 2; j++) {
                    int c = cbase + wn * 64 + nt * 8 + 2 * (lid & 3) + j;
                    float v = acc[mt][nt][h * 2 + j];
                    if (c < NCLS) {
                        if (c == tg) g_tgt[rbase + rloc] = v;
                        else         s += __expf(S_SCALE * v);
                    }
                }
            }
            // quad reduce (lanes 4t..4t+3 share rloc)
            s += __shfl_xor_sync(0xFFFFFFFFu, s, 1);
            s += __shfl_xor_sync(0xFFFFFFFFu, s, 2);
            if ((lid & 3) == 0) atomicAdd(&s_excl[rloc], s);
        }
    }
    __syncthreads();
    if (tid < BM) atomicAdd(&g_excl[rbase + tid], s_excl[tid]);
}

// ---------------- kernel 4: parallel final reduction ----------------
__global__ void finalize_part_kernel() {
    __shared__ float red[16];
    int tid = threadIdx.x;
    int i = blockIdx.x * 512 + tid;
    float t = g_tgt[i];
    t = fminf(fmaxf(t, -1.0f + 1e-7f), 1.0f - 1e-7f);
    float num = S_SCALE * (t * MARGIN_COS - sqrtf(fmaxf(1.0f - t * t, 0.0f)) * MARGIN_SIN);
    float den = expf(num) + g_excl[i];
    float s = num - logf(den);
#pragma unroll
    for (int o = 16; o; o >>= 1) s += __shfl_xor_sync(0xFFFFFFFFu, s, o);
    if ((tid & 31) == 0) red[tid >> 5] = s;
    __syncthreads();
    if (tid < 16) {
        float v = red[tid];
#pragma unroll
        for (int o = 8; o; o >>= 1) v += __shfl_xor_sync(0xFFFFu, v, o);
        if (tid == 0) atomicAdd(&g_sum, v);
    }
}

__global__ void write_out_kernel(float* __restrict__ out) {
    out[0] = -g_sum / (float)N_ROWS;
}

// ---------------- launch ----------------
extern "C" void kernel_launch(void* const* d_in, const int* in_sizes, int n_in,
                              void* d_out, int out_size) {
    const float* x      = (const float*)d_in[0];
    const float* W      = (const float*)d_in[1];
    const int*   target = (const int*)d_in[2];
    float*       out    = (float*)d_out;

    cudaFuncSetAttribute(arc_gemm_kernel,
                         cudaFuncAttributeMaxDynamicSharedMemorySize, SMEM_TOTAL);

    zero_sum_kernel<<<1, 1>>>();
    conv_w_kernel<<<(int)(((size_t)NCLS * DIM) / 1024), 256>>>(W);
    prep_x_kernel<<<N_ROWS / 8, 256>>>(x);
    arc_gemm_kernel<<<dim3(MTILES, NTILES), 256, SMEM_TOTAL>>>(target);
    finalize_part_kernel<<<N_ROWS / 512, 512>>>();
    write_out_kernel<<<1, 1>>>(out);
}

// round 5
// speedup vs baseline: 1.2051x; 1.2051x over previous
#include <cuda_runtime.h>
#include <cuda_bf16.h>
#include <cstdint>
#include <cstddef>

#define DEV_INLINE __device__ __forceinline__

// ---------------- problem constants (fixed shapes) ----------------
constexpr int N_ROWS = 4096;
constexpr int DIM    = 512;
constexpr int NCLS   = 50000;
constexpr float S_SCALE    = 30.0f;
constexpr float MARGIN_COS = 0.9210609940028851f;  // cos(0.4)
constexpr float MARGIN_SIN = 0.3894183423086505f;  // sin(0.4)

// ---------------- GEMM tiling ----------------
constexpr int BM = 128;
constexpr int BN = 256;
constexpr int BK = 64;                 // 64 bf16 = 128B rows (SW128 atom)
constexpr int NKI = DIM / BK;          // 8 k-iterations
constexpr int NSTAGE = 3;
constexpr int MTILES = N_ROWS / BM;                  // 32
constexpr int NTILES = (NCLS + BN - 1) / BN;         // 196 (last masked)
constexpr int NTHREADS = 512;                        // 16 warps, 4x4 warp grid

constexpr uint32_t A_STAGE = BM * 128;               // 16384
constexpr uint32_t B_STAGE = BN * 128;               // 32768
constexpr uint32_t SMEM_B0   = NSTAGE * A_STAGE;     // 49152
constexpr uint32_t SMEM_EXCL = SMEM_B0 + NSTAGE * B_STAGE;   // 147456
constexpr uint32_t SMEM_TG   = SMEM_EXCL + BM * 4;           // 147968
constexpr uint32_t SMEM_TOTAL = SMEM_TG + BM * 4;            // 148480

// ---------------- device scratch (allocation-free rule) ----------------
__device__ __nv_bfloat16 g_xbf[(size_t)N_ROWS * DIM];   // normalized x, bf16
__device__ __nv_bfloat16 g_wbf[(size_t)NCLS * DIM];     // W, bf16 (51MB, mostly L2)
__device__ float g_excl[N_ROWS];
__device__ float g_tgt[N_ROWS];
__device__ float g_sum;

// ---------------- helpers ----------------
DEV_INLINE uint32_t smem_u32(const void* p) { return (uint32_t)__cvta_generic_to_shared(p); }
DEV_INLINE uint32_t swz(uint32_t o) { return o ^ ((o >> 3) & 0x70); }

DEV_INLINE void cp16(uint32_t dst, const void* src) {
    asm volatile("cp.async.cg.shared.global [%0], [%1], 16;" :: "r"(dst), "l"(src));
}

DEV_INLINE void ldm_x4(uint32_t& r0, uint32_t& r1, uint32_t& r2, uint32_t& r3,
                       uint32_t addr) {
    asm volatile("ldmatrix.sync.aligned.m8n8.x4.shared.b16 {%0,%1,%2,%3}, [%4];"
                 : "=r"(r0), "=r"(r1), "=r"(r2), "=r"(r3) : "r"(addr));
}

DEV_INLINE void mma_bf16(float* d, const uint32_t* a, uint32_t b0, uint32_t b1) {
    asm volatile(
        "mma.sync.aligned.m16n8k16.row.col.f32.bf16.bf16.f32 "
        "{%0,%1,%2,%3}, {%4,%5,%6,%7}, {%8,%9}, {%0,%1,%2,%3};"
        : "+f"(d[0]), "+f"(d[1]), "+f"(d[2]), "+f"(d[3])
        : "r"(a[0]), "r"(a[1]), "r"(a[2]), "r"(a[3]), "r"(b0), "r"(b1));
}

// ---------------- kernel 0: zero the loss accumulator ----------------
__global__ void zero_sum_kernel() { g_sum = 0.0f; }

// ---------------- kernel 1: W fp32 -> bf16 ----------------
__global__ void conv_w_kernel(const float* __restrict__ W) {
    size_t i = ((size_t)blockIdx.x * blockDim.x + threadIdx.x) * 4;
    float4 v = *reinterpret_cast<const float4*>(W + i);
    *reinterpret_cast<__nv_bfloat162*>(g_wbf + i)     = __floats2bfloat162_rn(v.x, v.y);
    *reinterpret_cast<__nv_bfloat162*>(g_wbf + i + 2) = __floats2bfloat162_rn(v.z, v.w);
}

// ---------------- kernel 2: normalize x rows -> bf16 (+ zero excl) ----------------
__global__ void prep_x_kernel(const float* __restrict__ x) {
    int row = blockIdx.x * 8 + (threadIdx.x >> 5);
    int lid = threadIdx.x & 31;
    const float* xr = x + (size_t)row * DIM;
    float s = 0.0f;
#pragma unroll
    for (int j = 0; j < 16; j++) { float v = xr[lid + j * 32]; s += v * v; }
#pragma unroll
    for (int o = 16; o; o >>= 1) s += __shfl_xor_sync(0xFFFFFFFFu, s, o);
    float rn = rsqrtf(s);
    __nv_bfloat16* outr = g_xbf + (size_t)row * DIM;
#pragma unroll
    for (int j = 0; j < 16; j++) {
        int d = lid + j * 32;
        outr[d] = __float2bfloat16(xr[d] * rn);
    }
    if (lid == 0) g_excl[row] = 0.0f;   // re-zero on every graph replay
}

// ---------------- kernel 3: HMMA GEMM + fused arcface epilogue ----------------
// BM=128 x BN=256, 16 warps in 4x4 grid, 32x64 warp tiles, 3-stage cp.async.
__global__ void __launch_bounds__(NTHREADS, 1)
arc_gemm_kernel(const int* __restrict__ target) {
    extern __shared__ char smem[];
    const uint32_t sb = smem_u32(smem);
    const uint32_t sA = sb;
    const uint32_t sB = sb + SMEM_B0;
    float* s_excl = reinterpret_cast<float*>(smem + SMEM_EXCL);
    int*   s_tg   = reinterpret_cast<int*>(smem + SMEM_TG);

    const int tid = threadIdx.x;
    const int lid = tid & 31;
    const int wid = tid >> 5;
    const int wm  = wid & 3;          // 0..3  (m, 32 rows each)
    const int wn  = wid >> 2;         // 0..3  (n, 64 cols each)
    const int rbase = blockIdx.x * BM;
    const int cbase = blockIdx.y * BN;

    if (tid < BM) {
        s_excl[tid] = 0.0f;
        s_tg[tid]   = target[rbase + tid];
    }

    // cp.async chunking with 512 threads: 16B chunks; c_row 0..63, rows advance by 64
    const int c_row = tid >> 3;
    const int c_kb  = tid & 7;

    // ldmatrix address components (within-stage byte offsets; swizzled at use)
    const uint32_t a_row  = wm * 32 + (lid & 15);
    const uint32_t a_koff = (lid >> 4) * 16;
    const uint32_t b_row  = wn * 64 + (lid & 7) + ((lid >> 4) & 1) * 8;
    const uint32_t b_koff = ((lid >> 3) & 1) * 16;

    float acc[2][8][4];
#pragma unroll
    for (int mt = 0; mt < 2; mt++)
#pragma unroll
        for (int nt = 0; nt < 8; nt++)
#pragma unroll
            for (int j = 0; j < 4; j++) acc[mt][nt][j] = 0.0f;

    // ---- prefetch stages 0 and 1 ----
#pragma unroll
    for (int pk = 0; pk < 2; pk++) {
        const int k0 = pk * BK;
        const uint32_t sa = sA + pk * A_STAGE;
        const uint32_t sbb = sB + pk * B_STAGE;
        const __nv_bfloat16* xs = g_xbf + (size_t)rbase * DIM + k0;
#pragma unroll
        for (int i = 0; i < 2; i++) {
            int row = c_row + i * 64;
            cp16(sa + swz(row * 128 + c_kb * 16), xs + (size_t)row * DIM + c_kb * 8);
        }
        const __nv_bfloat16* ws = g_wbf + k0;
#pragma unroll
        for (int i = 0; i < 4; i++) {
            int row = c_row + i * 64;
            int c = cbase + row; c = (c < NCLS) ? c : (NCLS - 1);
            cp16(sbb + swz(row * 128 + c_kb * 16), ws + (size_t)c * DIM + c_kb * 8);
        }
        asm volatile("cp.async.commit_group;" ::: "memory");
    }

    int stage = 0;
    for (int k = 0; k < NKI; k++) {
        if (k == NKI - 1)
            asm volatile("cp.async.wait_group 0;" ::: "memory");
        else
            asm volatile("cp.async.wait_group 1;" ::: "memory");
        __syncthreads();

        if (k + 2 < NKI) {
            const int ps = (stage + 2 >= NSTAGE) ? stage + 2 - NSTAGE : stage + 2;
            const int k0 = (k + 2) * BK;
            const uint32_t sa = sA + ps * A_STAGE;
            const uint32_t sbb = sB + ps * B_STAGE;
            const __nv_bfloat16* xs = g_xbf + (size_t)rbase * DIM + k0;
#pragma unroll
            for (int i = 0; i < 2; i++) {
                int row = c_row + i * 64;
                cp16(sa + swz(row * 128 + c_kb * 16), xs + (size_t)row * DIM + c_kb * 8);
            }
            const __nv_bfloat16* ws = g_wbf + k0;
#pragma unroll
            for (int i = 0; i < 4; i++) {
                int row = c_row + i * 64;
                int c = cbase + row; c = (c < NCLS) ? c : (NCLS - 1);
                cp16(sbb + swz(row * 128 + c_kb * 16), ws + (size_t)c * DIM + c_kb * 8);
            }
            asm volatile("cp.async.commit_group;" ::: "memory");
        }

        const uint32_t abase = sA + stage * A_STAGE;
        const uint32_t bbase = sB + stage * B_STAGE;
        // ---- compute BK=64 as 4 k-steps of 16 ----
#pragma unroll
        for (int kk = 0; kk < 4; kk++) {
            uint32_t a[2][4];
#pragma unroll
            for (int mt = 0; mt < 2; mt++) {
                uint32_t addr = abase + swz((a_row + mt * 16) * 128 + kk * 32 + a_koff);
                ldm_x4(a[mt][0], a[mt][1], a[mt][2], a[mt][3], addr);
            }
            uint32_t b[8][2];
#pragma unroll
            for (int np = 0; np < 4; np++) {
                uint32_t r0, r1, r2, r3;
                uint32_t addr = bbase + swz((b_row + np * 16) * 128 + kk * 32 + b_koff);
                ldm_x4(r0, r1, r2, r3, addr);
                b[np * 2][0] = r0;     b[np * 2][1] = r1;
                b[np * 2 + 1][0] = r2; b[np * 2 + 1][1] = r3;
            }
#pragma unroll
            for (int mt = 0; mt < 2; mt++)
#pragma unroll
                for (int nt = 0; nt < 8; nt++)
                    mma_bf16(acc[mt][nt], a[mt], b[nt][0], b[nt][1]);
        }
        stage = (stage + 1 >= NSTAGE) ? 0 : stage + 1;
    }
    __syncthreads();

    // ---- fused epilogue from accumulator registers ----
    // c-frag: d0=(r,c0) d1=(r,c0+1) d2=(r+8,c0) d3=(r+8,c0+1); r=lid>>2, c0=2*(lid&3)
#pragma unroll
    for (int mt = 0; mt < 2; mt++) {
#pragma unroll
        for (int h = 0; h < 2; h++) {
            int rloc = wm * 32 + mt * 16 + (lid >> 2) + h * 8;
            int tg = s_tg[rloc];
            float s = 0.0f;
#pragma unroll
            for (int nt = 0; nt < 8; nt++) {
#pragma unroll
                for (int j = 0; j < 2; j++) {
                    int c = cbase + wn * 64 + nt * 8 + 2 * (lid & 3) + j;
                    float v = acc[mt][nt][h * 2 + j];
                    if (c < NCLS) {
                        if (c == tg) g_tgt[rbase + rloc] = v;
                        else         s += __expf(S_SCALE * v);
                    }
                }
            }
            // quad reduce (lanes 4t..4t+3 share rloc)
            s += __shfl_xor_sync(0xFFFFFFFFu, s, 1);
            s += __shfl_xor_sync(0xFFFFFFFFu, s, 2);
            if ((lid & 3) == 0) atomicAdd(&s_excl[rloc], s);
        }
    }
    __syncthreads();
    if (tid < BM) atomicAdd(&g_excl[rbase + tid], s_excl[tid]);
}

// ---------------- kernel 4: parallel final reduction ----------------
__global__ void finalize_part_kernel() {
    __shared__ float red[16];
    int tid = threadIdx.x;
    int i = blockIdx.x * 512 + tid;
    float t = g_tgt[i];
    t = fminf(fmaxf(t, -1.0f + 1e-7f), 1.0f - 1e-7f);
    float num = S_SCALE * (t * MARGIN_COS - sqrtf(fmaxf(1.0f - t * t, 0.0f)) * MARGIN_SIN);
    float den = expf(num) + g_excl[i];
    float s = num - logf(den);
#pragma unroll
    for (int o = 16; o; o >>= 1) s += __shfl_xor_sync(0xFFFFFFFFu, s, o);
    if ((tid & 31) == 0) red[tid >> 5] = s;
    __syncthreads();
    if (tid < 16) {
        float v = red[tid];
#pragma unroll
        for (int o = 8; o; o >>= 1) v += __shfl_xor_sync(0xFFFFu, v, o);
        if (tid == 0) atomicAdd(&g_sum, v);
    }
}

__global__ void write_out_kernel(float* __restrict__ out) {
    out[0] = -g_sum / (float)N_ROWS;
}

// ---------------- launch ----------------
extern "C" void kernel_launch(void* const* d_in, const int* in_sizes, int n_in,
                              void* d_out, int out_size) {
    const float* x      = (const float*)d_in[0];
    const float* W      = (const float*)d_in[1];
    const int*   target = (const int*)d_in[2];
    float*       out    = (float*)d_out;

    cudaFuncSetAttribute(arc_gemm_kernel,
                         cudaFuncAttributeMaxDynamicSharedMemorySize, SMEM_TOTAL);

    zero_sum_kernel<<<1, 1>>>();
    conv_w_kernel<<<(int)(((size_t)NCLS * DIM) / 1024), 256>>>(W);
    prep_x_kernel<<<N_ROWS / 8, 256>>>(x);
    arc_gemm_kernel<<<dim3(MTILES, NTILES), NTHREADS, SMEM_TOTAL>>>(target);
    finalize_part_kernel<<<N_ROWS / 512, 512>>>();
    write_out_kernel<<<1, 1>>>(out);
}

// round 6
// speedup vs baseline: 1.4752x; 1.2242x over previous
#include <cuda_runtime.h>
#include <cuda_bf16.h>
#include <cstdint>
#include <cstddef>

#define DEV_INLINE __device__ __forceinline__

// ---------------- problem constants (fixed shapes) ----------------
constexpr int N_ROWS = 4096;
constexpr int DIM    = 512;
constexpr int NCLS   = 50000;
constexpr float S_SCALE    = 30.0f;
constexpr float MARGIN_COS = 0.9210609940028851f;  // cos(0.4)
constexpr float MARGIN_SIN = 0.3894183423086505f;  // sin(0.4)

// ---------------- GEMM tiling ----------------
constexpr int BM = 128;
constexpr int BN = 128;
constexpr int BK = 64;                 // 64 bf16 = 128B rows (SW128 atom)
constexpr int NKI = DIM / BK;          // 8 k-iterations
constexpr int NSTAGE = 3;
constexpr int MTILES = N_ROWS / BM;                  // 32
constexpr int NTILES = (NCLS + BN - 1) / BN;         // 391 (last masked)

constexpr uint32_t A_STAGE = BM * 128;               // 16384
constexpr uint32_t B_STAGE = BN * 128;               // 16384
constexpr uint32_t STAGE_BYTES = A_STAGE + B_STAGE;  // 32768
constexpr uint32_t SMEM_EXCL = NSTAGE * STAGE_BYTES;         // 98304
constexpr uint32_t SMEM_TG   = SMEM_EXCL + BM * 4;           // 98816
constexpr uint32_t SMEM_TOTAL = SMEM_TG + BM * 4;            // 99328 (x2 CTA = 199KB)

// ---------------- device scratch (allocation-free rule) ----------------
__device__ __nv_bfloat16 g_xbf[(size_t)N_ROWS * DIM];   // normalized x, bf16
__device__ __nv_bfloat16 g_wbf[(size_t)NCLS * DIM];     // W, bf16 (51MB, mostly L2)
__device__ float g_excl[N_ROWS];
__device__ float g_tgt[N_ROWS];
__device__ float g_sum;

// ---------------- helpers ----------------
DEV_INLINE uint32_t smem_u32(const void* p) { return (uint32_t)__cvta_generic_to_shared(p); }
DEV_INLINE uint32_t swz(uint32_t o) { return o ^ ((o >> 3) & 0x70); }

DEV_INLINE void cp16(uint32_t dst, const void* src) {
    asm volatile("cp.async.cg.shared.global [%0], [%1], 16;" :: "r"(dst), "l"(src));
}

DEV_INLINE void ldm_x4(uint32_t& r0, uint32_t& r1, uint32_t& r2, uint32_t& r3,
                       uint32_t addr) {
    asm volatile("ldmatrix.sync.aligned.m8n8.x4.shared.b16 {%0,%1,%2,%3}, [%4];"
                 : "=r"(r0), "=r"(r1), "=r"(r2), "=r"(r3) : "r"(addr));
}

DEV_INLINE void mma_bf16(float* d, const uint32_t* a, uint32_t b0, uint32_t b1) {
    asm volatile(
        "mma.sync.aligned.m16n8k16.row.col.f32.bf16.bf16.f32 "
        "{%0,%1,%2,%3}, {%4,%5,%6,%7}, {%8,%9}, {%0,%1,%2,%3};"
        : "+f"(d[0]), "+f"(d[1]), "+f"(d[2]), "+f"(d[3])
        : "r"(a[0]), "r"(a[1]), "r"(a[2]), "r"(a[3]), "r"(b0), "r"(b1));
}

// ---------------- kernel 0: zero the loss accumulator ----------------
__global__ void zero_sum_kernel() { g_sum = 0.0f; }

// ---------------- kernel 1: W fp32 -> bf16 ----------------
__global__ void conv_w_kernel(const float* __restrict__ W) {
    size_t i = ((size_t)blockIdx.x * blockDim.x + threadIdx.x) * 4;
    float4 v = *reinterpret_cast<const float4*>(W + i);
    *reinterpret_cast<__nv_bfloat162*>(g_wbf + i)     = __floats2bfloat162_rn(v.x, v.y);
    *reinterpret_cast<__nv_bfloat162*>(g_wbf + i + 2) = __floats2bfloat162_rn(v.z, v.w);
}

// ---------------- kernel 2: normalize x rows -> bf16 (+ zero excl) ----------------
__global__ void prep_x_kernel(const float* __restrict__ x) {
    int row = blockIdx.x * 8 + (threadIdx.x >> 5);
    int lid = threadIdx.x & 31;
    const float* xr = x + (size_t)row * DIM;
    float s = 0.0f;
#pragma unroll
    for (int j = 0; j < 16; j++) { float v = xr[lid + j * 32]; s += v * v; }
#pragma unroll
    for (int o = 16; o; o >>= 1) s += __shfl_xor_sync(0xFFFFFFFFu, s, o);
    float rn = rsqrtf(s);
    __nv_bfloat16* outr = g_xbf + (size_t)row * DIM;
#pragma unroll
    for (int j = 0; j < 16; j++) {
        int d = lid + j * 32;
        outr[d] = __float2bfloat16(xr[d] * rn);
    }
    if (lid == 0) g_excl[row] = 0.0f;   // re-zero on every graph replay
}

// ---------------- kernel 3: HMMA GEMM + fused arcface epilogue ----------------
// BM=128 x BN=128, 8 warps in 2x4 grid, 64x32 warp tiles, 2 CTAs/SM, 3-stage.
__global__ void __launch_bounds__(256, 2)
arc_gemm_kernel(const int* __restrict__ target) {
    extern __shared__ char smem[];
    const uint32_t sb = smem_u32(smem);
    float* s_excl = reinterpret_cast<float*>(smem + SMEM_EXCL);
    int*   s_tg   = reinterpret_cast<int*>(smem + SMEM_TG);

    const int tid = threadIdx.x;
    const int lid = tid & 31;
    const int wid = tid >> 5;
    const int wm  = wid & 1;          // 0..1  (m, 64 rows each)
    const int wn  = wid >> 1;         // 0..3  (n, 32 cols each)
    const int rbase = blockIdx.x * BM;
    const int cbase = blockIdx.y * BN;

    if (tid < BM) {
        s_excl[tid] = 0.0f;
        s_tg[tid]   = target[rbase + tid];
    }

    // cp.async chunking: 16B chunks; chunk = tid + i*256; row = chunk>>3, kb = chunk&7
    const int c_row = tid >> 3;
    const int c_kb  = tid & 7;

    // ldmatrix address components (within-stage byte offsets; swizzled at use)
    const uint32_t a_row  = wm * 64 + (lid & 15);
    const uint32_t a_koff = (lid >> 4) * 16;
    const uint32_t b_row  = wn * 32 + (lid & 7) + ((lid >> 4) & 1) * 8;
    const uint32_t b_koff = ((lid >> 3) & 1) * 16;

    float acc[4][4][4];
#pragma unroll
    for (int mt = 0; mt < 4; mt++)
#pragma unroll
        for (int nt = 0; nt < 4; nt++)
#pragma unroll
            for (int j = 0; j < 4; j++) acc[mt][nt][j] = 0.0f;

    // ---- prefetch stages 0 and 1 ----
#pragma unroll
    for (int pk = 0; pk < 2; pk++) {
        const int k0 = pk * BK;
        const uint32_t sa  = sb + pk * STAGE_BYTES;
        const uint32_t sbb = sa + A_STAGE;
        const __nv_bfloat16* xs = g_xbf + (size_t)rbase * DIM + k0;
#pragma unroll
        for (int i = 0; i < 4; i++) {
            int row = c_row + i * 32;
            cp16(sa + swz(row * 128 + c_kb * 16), xs + (size_t)row * DIM + c_kb * 8);
        }
        const __nv_bfloat16* ws = g_wbf + k0;
#pragma unroll
        for (int i = 0; i < 4; i++) {
            int row = c_row + i * 32;
            int c = cbase + row; c = (c < NCLS) ? c : (NCLS - 1);
            cp16(sbb + swz(row * 128 + c_kb * 16), ws + (size_t)c * DIM + c_kb * 8);
        }
        asm volatile("cp.async.commit_group;" ::: "memory");
    }

    int stage = 0;
    for (int k = 0; k < NKI; k++) {
        if (k == NKI - 1)
            asm volatile("cp.async.wait_group 0;" ::: "memory");
        else
            asm volatile("cp.async.wait_group 1;" ::: "memory");
        __syncthreads();

        if (k + 2 < NKI) {
            const int ps = (stage + 2 >= NSTAGE) ? stage + 2 - NSTAGE : stage + 2;
            const int k0 = (k + 2) * BK;
            const uint32_t sa  = sb + ps * STAGE_BYTES;
            const uint32_t sbb = sa + A_STAGE;
            const __nv_bfloat16* xs = g_xbf + (size_t)rbase * DIM + k0;
#pragma unroll
            for (int i = 0; i < 4; i++) {
                int row = c_row + i * 32;
                cp16(sa + swz(row * 128 + c_kb * 16), xs + (size_t)row * DIM + c_kb * 8);
            }
            const __nv_bfloat16* ws = g_wbf + k0;
#pragma unroll
            for (int i = 0; i < 4; i++) {
                int row = c_row + i * 32;
                int c = cbase + row; c = (c < NCLS) ? c : (NCLS - 1);
                cp16(sbb + swz(row * 128 + c_kb * 16), ws + (size_t)c * DIM + c_kb * 8);
            }
            asm volatile("cp.async.commit_group;" ::: "memory");
        }

        const uint32_t abase = sb + stage * STAGE_BYTES;
        const uint32_t bbase = abase + A_STAGE;
        // ---- compute BK=64 as 4 k-steps of 16 ----
#pragma unroll
        for (int kk = 0; kk < 4; kk++) {
            uint32_t a[4][4];
#pragma unroll
            for (int mt = 0; mt < 4; mt++) {
                uint32_t addr = abase + swz((a_row + mt * 16) * 128 + kk * 32 + a_koff);
                ldm_x4(a[mt][0], a[mt][1], a[mt][2], a[mt][3], addr);
            }
            uint32_t b[4][2];
#pragma unroll
            for (int np = 0; np < 2; np++) {
                uint32_t r0, r1, r2, r3;
                uint32_t addr = bbase + swz((b_row + np * 16) * 128 + kk * 32 + b_koff);
                ldm_x4(r0, r1, r2, r3, addr);
                b[np * 2][0] = r0;     b[np * 2][1] = r1;
                b[np * 2 + 1][0] = r2; b[np * 2 + 1][1] = r3;
            }
#pragma unroll
            for (int mt = 0; mt < 4; mt++)
#pragma unroll
                for (int nt = 0; nt < 4; nt++)
                    mma_bf16(acc[mt][nt], a[mt], b[nt][0], b[nt][1]);
        }
        stage = (stage + 1 >= NSTAGE) ? 0 : stage + 1;
    }
    __syncthreads();

    // ---- fused epilogue from accumulator registers ----
    // c-frag: d0=(r,c0) d1=(r,c0+1) d2=(r+8,c0) d3=(r+8,c0+1); r=lid>>2, c0=2*(lid&3)
#pragma unroll
    for (int mt = 0; mt < 4; mt++) {
#pragma unroll
        for (int h = 0; h < 2; h++) {
            int rloc = wm * 64 + mt * 16 + (lid >> 2) + h * 8;
            int tg = s_tg[rloc];
            float s = 0.0f;
#pragma unroll
            for (int nt = 0; nt < 4; nt++) {
#pragma unroll
                for (int j = 0; j < 2; j++) {
                    int c = cbase + wn * 32 + nt * 8 + 2 * (lid & 3) + j;
                    float v = acc[mt][nt][h * 2 + j];
                    if (c < NCLS) {
                        if (c == tg) g_tgt[rbase + rloc] = v;
                        else         s += __expf(S_SCALE * v);
                    }
                }
            }
            // quad reduce (lanes 4t..4t+3 share rloc)
            s += __shfl_xor_sync(0xFFFFFFFFu, s, 1);
            s += __shfl_xor_sync(0xFFFFFFFFu, s, 2);
            if ((lid & 3) == 0) atomicAdd(&s_excl[rloc], s);
        }
    }
    __syncthreads();
    if (tid < BM) atomicAdd(&g_excl[rbase + tid], s_excl[tid]);
}

// ---------------- kernel 4: parallel final reduction ----------------
__global__ void finalize_part_kernel() {
    __shared__ float red[16];
    int tid = threadIdx.x;
    int i = blockIdx.x * 512 + tid;
    float t = g_tgt[i];
    t = fminf(fmaxf(t, -1.0f + 1e-7f), 1.0f - 1e-7f);
    float num = S_SCALE * (t * MARGIN_COS - sqrtf(fmaxf(1.0f - t * t, 0.0f)) * MARGIN_SIN);
    float den = expf(num) + g_excl[i];
    float s = num - logf(den);
#pragma unroll
    for (int o = 16; o; o >>= 1) s += __shfl_xor_sync(0xFFFFFFFFu, s, o);
    if ((tid & 31) == 0) red[tid >> 5] = s;
    __syncthreads();
    if (tid < 16) {
        float v = red[tid];
#pragma unroll
        for (int o = 8; o; o >>= 1) v += __shfl_xor_sync(0xFFFFu, v, o);
        if (tid == 0) atomicAdd(&g_sum, v);
    }
}

__global__ void write_out_kernel(float* __restrict__ out) {
    out[0] = -g_sum / (float)N_ROWS;
}

// ---------------- launch ----------------
extern "C" void kernel_launch(void* const* d_in, const int* in_sizes, int n_in,
                              void* d_out, int out_size) {
    const float* x      = (const float*)d_in[0];
    const float* W      = (const float*)d_in[1];
    const int*   target = (const int*)d_in[2];
    float*       out    = (float*)d_out;

    cudaFuncSetAttribute(arc_gemm_kernel,
                         cudaFuncAttributeMaxDynamicSharedMemorySize, SMEM_TOTAL);

    zero_sum_kernel<<<1, 1>>>();
    conv_w_kernel<<<(int)(((size_t)NCLS * DIM) / 1024), 256>>>(W);
    prep_x_kernel<<<N_ROWS / 8, 256>>>(x);
    arc_gemm_kernel<<<dim3(MTILES, NTILES), 256, SMEM_TOTAL>>>(target);
    finalize_part_kernel<<<N_ROWS / 512, 512>>>();
    write_out_kernel<<<1, 1>>>(out);
}